// round 5
// baseline (speedup 1.0000x reference)
#include <cuda_runtime.h>
#include <math.h>

// Problem constants
static const int BB = 64;    // batch
static const int SL = 512;   // sequence length
static const int HD = 512;   // hidden
static const int G4 = 2048;  // 4*H gates

// ------------------- device scratch (no allocations allowed) -------------------
__device__ float g_K1[(size_t)BB * SL * HD];   // key projection, row = b*SL+s
__device__ float g_Q [(size_t)SL * BB * HD];   // query,          row = t*BB+b
__device__ float g_Hs[(size_t)SL * BB * HD];   // h sequence,     row = t*BB+b
__device__ float g_hT[2][HD * BB];             // transposed h (double buffer) [j][b]
__device__ float g_cT[HD * BB];                // transposed c [j][b]
__device__ float g_Xu[2][HD];                  // x' chain (batch independent)
__device__ float g_XG[2][G4];                  // XG[t] = Xu[t]@W_ih^T + b_ih + b_hh
__device__ float g_L [(size_t)BB * SL * SL];   // logits fallback scratch

// ------------------- accurate fast activations (flag-independent) -------------------
__device__ __forceinline__ float sigm_f(float x) {
    float e = __expf(-x);
    return __fdividef(1.0f, 1.0f + e);
}
__device__ __forceinline__ float tanh_f(float x) {
    float e = __expf(2.0f * x);                 // +inf for big x -> 1, 0 for very negative -> -1
    return 1.0f - __fdividef(2.0f, e + 1.0f);
}

// ------------------- prologue: Xu[0], Xu[1], XG[0], transpose h0/c0 -------------------
__global__ void __launch_bounds__(256) prologue_kernel(
    const float* __restrict__ h0, const float* __restrict__ c0,
    const float* __restrict__ W_in, const float* __restrict__ b_in,
    const float* __restrict__ W_ih, const float* __restrict__ b_ih,
    const float* __restrict__ b_hh)
{
    int blk = blockIdx.x, tid = threadIdx.x;
    if (blk == 0) {
        // Xu[0] = sigmoid(b_in);  Xu[1] = sigmoid(Xu[0] @ W_in^T + b_in)
        __shared__ float x0s[HD];
        for (int i = tid; i < HD; i += 256) {
            float x = sigm_f(b_in[i]);
            x0s[i] = x;
            g_Xu[0][i] = x;
        }
        __syncthreads();
        for (int row = tid; row < HD; row += 256) {
            float acc = b_in[row];
            const float* wr = W_in + (size_t)row * HD;
            for (int k = 0; k < HD; k += 4) {
                float4 w4 = *(const float4*)&wr[k];
                acc = fmaf(x0s[k+0], w4.x, acc);
                acc = fmaf(x0s[k+1], w4.y, acc);
                acc = fmaf(x0s[k+2], w4.z, acc);
                acc = fmaf(x0s[k+3], w4.w, acc);
            }
            g_Xu[1][row] = sigm_f(acc);
        }
    } else if (blk <= 16) {
        // XG[0] = Xu[0] @ W_ih^T + b_ih + b_hh   (128 rows per block)
        __shared__ float x0s[HD];
        for (int i = tid; i < HD; i += 256) x0s[i] = sigm_f(b_in[i]);
        __syncthreads();
        if (tid < 128) {
            int row = (blk - 1) * 128 + tid;
            float acc = b_ih[row] + b_hh[row];
            const float* wr = W_ih + (size_t)row * HD;
            for (int k = 0; k < HD; k += 4) {
                float4 w4 = *(const float4*)&wr[k];
                acc = fmaf(x0s[k+0], w4.x, acc);
                acc = fmaf(x0s[k+1], w4.y, acc);
                acc = fmaf(x0s[k+2], w4.z, acc);
                acc = fmaf(x0s[k+3], w4.w, acc);
            }
            g_XG[0][row] = acc;
        }
    } else if (blk <= 20) {
        // transpose h0 -> g_hT[0][j][b]
        int j0 = (blk - 17) * 128;
        for (int idx = tid; idx < 128 * BB; idx += 256) {
            int j = j0 + (idx >> 6), b = idx & 63;
            g_hT[0][j * BB + b] = h0[(size_t)b * HD + j];
        }
    } else if (blk <= 24) {
        // transpose c0 -> g_cT[j][b]
        int j0 = (blk - 21) * 128;
        for (int idx = tid; idx < 128 * BB; idx += 256) {
            int j = j0 + (idx >> 6), b = idx & 63;
            g_cT[j * BB + b] = c0[(size_t)b * HD + j];
        }
    }
}

// ------------------- one recurrence step (one launch per t) -------------------
// blocks 0..127  : gates GEMV tile (16 gate rows = 4 h-dims x {i,f,g,o}) x 64 batches,
//                  fused LSTM pointwise update for those 4 dims.
// blocks 128..143: XG[t+1] = Xu[t+1] @ W_ih^T + b_ih + b_hh   (pipelined)
// blocks 144..147: Xu[t+2] = sigmoid(Xu[t+1] @ W_in^T + b_in) (pipelined)
__global__ void __launch_bounds__(256) step_kernel(
    const float* __restrict__ W_hh, const float* __restrict__ W_ih,
    const float* __restrict__ W_in, const float* __restrict__ b_in,
    const float* __restrict__ b_ih, const float* __restrict__ b_hh,
    int t)
{
    __shared__ __align__(16) float pool[16 * 512 + 32 * 64 + 16 * 64]; // 45 KB
    int blk = blockIdx.x, tid = threadIdx.x;
    const float* hT = g_hT[t & 1];

    if (blk < 128) {
        float (*Wsh)[512] = (float(*)[512])pool;
        float (*hsh)[64]  = (float(*)[64])(pool + 16 * 512);
        float (*gsh)[64]  = (float(*)[64])(pool + 16 * 512 + 32 * 64);
        int jt = blk;  // h-dims [4jt, 4jt+4)

        // Load 16 W_hh rows (gate rows q*512 + 4jt + jl) into smem: 32 KB
        #pragma unroll
        for (int i = 0; i < 8; i++) {
            int idx = tid + 256 * i;        // float4 index (2048 total)
            int r   = idx >> 7;             // 128 float4 per row
            int c4  = idx & 127;
            int gr  = (r >> 2) * 512 + 4 * jt + (r & 3);
            *(float4*)&Wsh[r][c4 * 4] = *(const float4*)&W_hh[(size_t)gr * 512 + c4 * 4];
        }

        int r   = tid >> 4;   // local gate row 0..15
        int col = tid & 15;   // batch group (4 batches)
        float a0 = 0.f, a1 = 0.f, a2 = 0.f, a3 = 0.f;
        const float* wrow = &Wsh[0][0] + r * 512;
        const float* hbase = &hsh[0][0] + col * 4;

        for (int kc = 0; kc < 16; kc++) {
            __syncthreads();   // guards Wsh (kc=0) and hsh reuse (kc>0)
            #pragma unroll
            for (int i = 0; i < 2; i++) {
                int idx = tid + 256 * i;    // 512 float4
                int row = idx >> 4, c4 = idx & 15;
                *(float4*)&hsh[row][c4 * 4] =
                    *(const float4*)&hT[(kc * 32 + row) * 64 + c4 * 4];
            }
            __syncthreads();
            #pragma unroll
            for (int kk = 0; kk < 32; kk++) {
                float w = wrow[kc * 32 + kk];
                float4 hv = *(const float4*)(hbase + kk * 64);
                a0 = fmaf(w, hv.x, a0);
                a1 = fmaf(w, hv.y, a1);
                a2 = fmaf(w, hv.z, a2);
                a3 = fmaf(w, hv.w, a3);
            }
        }

        int gr = (r >> 2) * 512 + 4 * jt + (r & 3);
        float xg = g_XG[t & 1][gr];
        gsh[r][col * 4 + 0] = a0 + xg;
        gsh[r][col * 4 + 1] = a1 + xg;
        gsh[r][col * 4 + 2] = a2 + xg;
        gsh[r][col * 4 + 3] = a3 + xg;
        __syncthreads();

        // Pointwise LSTM update: 4 dims x 64 batches = 256 values, one per thread
        int jl = tid >> 6, b = tid & 63;
        float iv = gsh[0 + jl][b];
        float fv = gsh[4 + jl][b];
        float gv = gsh[8 + jl][b];
        float ov = gsh[12 + jl][b];
        int j = 4 * jt + jl;
        float c_old = g_cT[j * 64 + b];
        float cn = fmaf(sigm_f(fv), c_old, sigm_f(iv) * tanh_f(gv));
        float hn = sigm_f(ov) * tanh_f(cn);
        g_cT[j * 64 + b] = cn;
        g_hT[(t + 1) & 1][j * 64 + b] = hn;
        g_Hs[((size_t)t * 64 + b) * 512 + j] = hn;

    } else if (blk < 144) {
        // XG[t+1] from Xu[t+1]
        float* xsh = pool;
        const float* xu = g_Xu[(t + 1) & 1];
        for (int i = tid; i < 512; i += 256) xsh[i] = xu[i];
        __syncthreads();
        if (tid < 128) {
            int row = (blk - 128) * 128 + tid;
            float acc = b_ih[row] + b_hh[row];
            const float* wr = W_ih + (size_t)row * 512;
            for (int k = 0; k < 512; k += 4) {
                float4 w4 = *(const float4*)&wr[k];
                acc = fmaf(xsh[k+0], w4.x, acc);
                acc = fmaf(xsh[k+1], w4.y, acc);
                acc = fmaf(xsh[k+2], w4.z, acc);
                acc = fmaf(xsh[k+3], w4.w, acc);
            }
            g_XG[(t + 1) & 1][row] = acc;
        }
    } else {
        // Xu[t+2] from Xu[t+1]
        float* xsh = pool;
        const float* xu = g_Xu[(t + 1) & 1];
        for (int i = tid; i < 512; i += 256) xsh[i] = xu[i];
        __syncthreads();
        if (tid < 128) {
            int row = (blk - 144) * 128 + tid;
            float acc = b_in[row];
            const float* wr = W_in + (size_t)row * 512;
            for (int k = 0; k < 512; k += 4) {
                float4 w4 = *(const float4*)&wr[k];
                acc = fmaf(xsh[k+0], w4.x, acc);
                acc = fmaf(xsh[k+1], w4.y, acc);
                acc = fmaf(xsh[k+2], w4.z, acc);
                acc = fmaf(xsh[k+3], w4.w, acc);
            }
            g_Xu[t & 1][row] = sigm_f(acc);   // (t+2)&1 == t&1
        }
    }
}

// ------------------- SGEMM NT: C[M][512] = A[M][512] * W[512][512]^T + bias -------------------
// 128x128 block tile, BK=8, 256 threads, 8x8 register tile.
__global__ void __launch_bounds__(256) sgemm_nt(
    const float* __restrict__ A, const float* __restrict__ W,
    const float* __restrict__ bias, float* __restrict__ C)
{
    __shared__ __align__(16) float As[8][128];
    __shared__ __align__(16) float Ws[8][128];
    int bm = blockIdx.y << 7, bn = blockIdx.x << 7;
    int tid = threadIdx.x;
    int tx = tid & 15, ty = tid >> 4;
    int lr = tid >> 1, lc = (tid & 1) << 2;

    float acc[8][8];
    #pragma unroll
    for (int i = 0; i < 8; i++)
        #pragma unroll
        for (int j = 0; j < 8; j++) acc[i][j] = 0.f;

    for (int k0 = 0; k0 < 512; k0 += 8) {
        float4 av = *(const float4*)&A[(size_t)(bm + lr) * 512 + k0 + lc];
        float4 wv = *(const float4*)&W[(size_t)(bn + lr) * 512 + k0 + lc];
        As[lc + 0][lr] = av.x; As[lc + 1][lr] = av.y;
        As[lc + 2][lr] = av.z; As[lc + 3][lr] = av.w;
        Ws[lc + 0][lr] = wv.x; Ws[lc + 1][lr] = wv.y;
        Ws[lc + 2][lr] = wv.z; Ws[lc + 3][lr] = wv.w;
        __syncthreads();
        #pragma unroll
        for (int kk = 0; kk < 8; kk++) {
            float a[8], bb[8];
            *(float4*)&a[0]  = *(const float4*)&As[kk][ty * 8];
            *(float4*)&a[4]  = *(const float4*)&As[kk][ty * 8 + 4];
            *(float4*)&bb[0] = *(const float4*)&Ws[kk][tx * 8];
            *(float4*)&bb[4] = *(const float4*)&Ws[kk][tx * 8 + 4];
            #pragma unroll
            for (int i = 0; i < 8; i++)
                #pragma unroll
                for (int j = 0; j < 8; j++)
                    acc[i][j] = fmaf(a[i], bb[j], acc[i][j]);
        }
        __syncthreads();
    }
    #pragma unroll
    for (int i = 0; i < 8; i++) {
        size_t off = (size_t)(bm + ty * 8 + i) * 512 + bn + tx * 8;
        #pragma unroll
        for (int j = 0; j < 8; j++)
            C[off + j] = acc[i][j] + bias[bn + tx * 8 + j];
    }
}

// ------------------- attention: u[b,t,s] = tanh(K1[b,s,:]+Q[t,b,:]) . v + b_v -------------------
// block = 32 t x 32 s tile for one b; h chunked by 64 through smem.
// mask read as 32-bit words: nonzero bits <=> True for BOTH int32 and float32
// encodings of the reference bool mask.
__global__ void __launch_bounds__(1024) attn_kernel(
    const float* __restrict__ v, const float* __restrict__ b_v,
    const unsigned int* __restrict__ mask32, float* __restrict__ out)
{
    __shared__ float Ksh[32][65];
    __shared__ float Qsh[32][65];
    __shared__ float vsh[64];
    int b  = blockIdx.z;
    int t0 = blockIdx.y << 5;
    int s0 = blockIdx.x << 5;
    int tid = threadIdx.x;
    int sl = tid & 31, tl = tid >> 5;

    float acc = 0.f;
    for (int h0 = 0; h0 < 512; h0 += 64) {
        if (tid < 64) vsh[tid] = v[h0 + tid];
        #pragma unroll
        for (int i = 0; i < 2; i++) {
            int id = tid + i * 1024;
            int row = id >> 6, cc = id & 63;
            Ksh[row][cc] = g_K1[((size_t)b * 512 + s0 + row) * 512 + h0 + cc];
            Qsh[row][cc] = g_Q[((size_t)(t0 + row) * 64 + b) * 512 + h0 + cc];
        }
        __syncthreads();
        #pragma unroll
        for (int h = 0; h < 64; h++) {
            float x = Ksh[sl][h] + Qsh[tl][h];
            acc = fmaf(tanh_f(x), vsh[h], acc);
        }
        __syncthreads();
    }
    float u = acc + b_v[0];
    int s = s0 + sl;
    if (mask32[b * 512 + s] == 0u) u = -1e9f;
    out[((size_t)b * 512 + t0 + tl) * 512 + s] = u;
}

// ------------------- argmax over last dim (first-max tie rule, like jnp.argmax) -------------------
__global__ void __launch_bounds__(256) argmax_kernel(
    const float* __restrict__ logits, float* __restrict__ outf,
    int* __restrict__ outi, int as_float)
{
    int row = blockIdx.x * 8 + (threadIdx.x >> 5);   // one warp per (b,t) row
    int lane = threadIdx.x & 31;
    const float* p = logits + (size_t)row * 512;
    float best = -INFINITY; int bi = 0;
    for (int s = lane; s < 512; s += 32) {
        float vv = p[s];
        if (vv > best) { best = vv; bi = s; }    // strict > keeps first max in-lane
    }
    #pragma unroll
    for (int off = 16; off; off >>= 1) {
        float ov = __shfl_down_sync(0xffffffffu, best, off);
        int   oi = __shfl_down_sync(0xffffffffu, bi,   off);
        if (ov > best || (ov == best && oi < bi)) { best = ov; bi = oi; }
    }
    if (lane == 0) {
        if (as_float) outf[row] = (float)bi;
        else          outi[row] = bi;
    }
}

// ------------------- launcher -------------------
extern "C" void kernel_launch(void* const* d_in, const int* in_sizes, int n_in,
                              void* d_out, int out_size) {
    const float* enc  = (const float*)d_in[0];
    const unsigned int* mask32 = (const unsigned int*)d_in[1];
    const float* h0   = (const float*)d_in[2];
    const float* c0   = (const float*)d_in[3];
    const float* W_in = (const float*)d_in[4];
    const float* b_in = (const float*)d_in[5];
    const float* W_ih = (const float*)d_in[6];
    const float* b_ih = (const float*)d_in[7];
    const float* W_hh = (const float*)d_in[8];
    const float* b_hh = (const float*)d_in[9];
    const float* W1   = (const float*)d_in[10];
    const float* b1   = (const float*)d_in[11];
    const float* W2   = (const float*)d_in[12];
    const float* b2   = (const float*)d_in[13];
    const float* v    = (const float*)d_in[14];
    const float* b_v  = (const float*)d_in[15];
    (void)in_sizes; (void)n_in;

    float *pK1, *pQ, *pHs, *pL;
    cudaGetSymbolAddress((void**)&pK1, g_K1);
    cudaGetSymbolAddress((void**)&pQ,  g_Q);
    cudaGetSymbolAddress((void**)&pHs, g_Hs);
    cudaGetSymbolAddress((void**)&pL,  g_L);

    prologue_kernel<<<25, 256>>>(h0, c0, W_in, b_in, W_ih, b_ih, b_hh);
    sgemm_nt<<<dim3(4, 256), 256>>>(enc, W1, b1, pK1);          // K1

    for (int t = 0; t < SL; t++)
        step_kernel<<<148, 256>>>(W_hh, W_ih, W_in, b_in, b_ih, b_hh, t);

    sgemm_nt<<<dim3(4, 256), 256>>>(pHs, W2, b2, pQ);           // Q

    const long long NL = (long long)BB * SL * SL;               // 16,777,216
    float* ldst = ((long long)out_size >= NL) ? (float*)d_out : pL;
    attn_kernel<<<dim3(16, 16, 64), 1024>>>(v, b_v, mask32, ldst);

    if ((long long)out_size >= NL + BB * SL) {
        argmax_kernel<<<4096, 256>>>(ldst, (float*)d_out + NL, nullptr, 1);
    } else if ((long long)out_size < NL) {
        argmax_kernel<<<4096, 256>>>(ldst, nullptr, (int*)d_out, 0);
    }
}

// round 6
// speedup vs baseline: 1.3255x; 1.3255x over previous
#include <cuda_runtime.h>
#include <math.h>

// Problem constants
static const int BB = 64;    // batch
static const int SL = 512;   // sequence length
static const int HD = 512;   // hidden
static const int G4 = 2048;  // 4*H gates
#define NBLK 128             // persistent blocks (<=148 SMs -> all resident)

// ------------------- device scratch (no allocations allowed) -------------------
__device__ float g_K1[(size_t)BB * SL * HD];   // key projection, row = b*SL+s
__device__ float g_Q [(size_t)SL * BB * HD];   // query,          row = t*BB+b
__device__ float g_Hs[(size_t)SL * BB * HD];   // h sequence,     row = t*BB+b
__device__ float g_hT[2][HD * BB];             // transposed h (double buffer) [j][b]
__device__ float g_Xu[2][HD];                  // x' chain (batch independent)
__device__ float g_XG[2][G4];                  // XG[t] = Xu[t]@W_ih^T + b_ih + b_hh
__device__ float g_L [(size_t)BB * SL * SL];   // logits fallback scratch

// grid barrier state (zero-initialized at module load; gen is monotonic)
__device__ unsigned int g_bar_count;
__device__ volatile unsigned int g_bar_gen;

// ------------------- accurate fast activations (flag-independent) -------------------
__device__ __forceinline__ float sigm_f(float x) {
    float e = __expf(-x);
    return __fdividef(1.0f, 1.0f + e);
}
__device__ __forceinline__ float tanh_f(float x) {
    float e = __expf(2.0f * x);                 // +inf for big x -> 1, 0 for very negative -> -1
    return 1.0f - __fdividef(2.0f, e + 1.0f);
}

// packed fp32x2 FMA (FFMA2) -- not emitted by ptxas from C++, PTX-only
__device__ __forceinline__ void ffma2(unsigned long long& d, unsigned long long a,
                                      unsigned long long b) {
    asm("fma.rn.f32x2 %0, %1, %2, %0;" : "+l"(d) : "l"(a), "l"(b));
}

// device-wide barrier: all NBLK blocks resident (1 CTA/SM guaranteed by smem size)
__device__ __forceinline__ void grid_barrier() {
    __threadfence();                 // publish this thread's stores to L2
    __syncthreads();
    if (threadIdx.x == 0) {
        unsigned int my = g_bar_gen;
        if (atomicAdd(&g_bar_count, 1u) == NBLK - 1u) {
            atomicExch(&g_bar_count, 0u);
            __threadfence();
            g_bar_gen = my + 1u;
        } else {
            while (g_bar_gen == my) { }
        }
        __threadfence();
    }
    __syncthreads();
}

// ------------------- prologue: Xu[0], Xu[1], XG[0], transpose h0 -------------------
__global__ void __launch_bounds__(256) prologue_kernel(
    const float* __restrict__ h0,
    const float* __restrict__ W_in, const float* __restrict__ b_in,
    const float* __restrict__ W_ih, const float* __restrict__ b_ih,
    const float* __restrict__ b_hh)
{
    int blk = blockIdx.x, tid = threadIdx.x;
    if (blk == 0) {
        // Xu[0] = sigmoid(b_in);  Xu[1] = sigmoid(Xu[0] @ W_in^T + b_in)
        __shared__ float x0s[HD];
        for (int i = tid; i < HD; i += 256) {
            float x = sigm_f(b_in[i]);
            x0s[i] = x;
            g_Xu[0][i] = x;
        }
        __syncthreads();
        for (int row = tid; row < HD; row += 256) {
            float acc = b_in[row];
            const float* wr = W_in + (size_t)row * HD;
            for (int k = 0; k < HD; k += 4) {
                float4 w4 = *(const float4*)&wr[k];
                acc = fmaf(x0s[k+0], w4.x, acc);
                acc = fmaf(x0s[k+1], w4.y, acc);
                acc = fmaf(x0s[k+2], w4.z, acc);
                acc = fmaf(x0s[k+3], w4.w, acc);
            }
            g_Xu[1][row] = sigm_f(acc);
        }
    } else if (blk <= 16) {
        // XG[0] = Xu[0] @ W_ih^T + b_ih + b_hh   (128 rows per block)
        __shared__ float x0s[HD];
        for (int i = tid; i < HD; i += 256) x0s[i] = sigm_f(b_in[i]);
        __syncthreads();
        if (tid < 128) {
            int row = (blk - 1) * 128 + tid;
            float acc = b_ih[row] + b_hh[row];
            const float* wr = W_ih + (size_t)row * HD;
            for (int k = 0; k < HD; k += 4) {
                float4 w4 = *(const float4*)&wr[k];
                acc = fmaf(x0s[k+0], w4.x, acc);
                acc = fmaf(x0s[k+1], w4.y, acc);
                acc = fmaf(x0s[k+2], w4.z, acc);
                acc = fmaf(x0s[k+3], w4.w, acc);
            }
            g_XG[0][row] = acc;
        }
    } else if (blk <= 20) {
        // transpose h0 -> g_hT[0][j][b]
        int j0 = (blk - 17) * 128;
        for (int idx = tid; idx < 128 * BB; idx += 256) {
            int j = j0 + (idx >> 6), b = idx & 63;
            g_hT[0][j * BB + b] = h0[(size_t)b * HD + j];
        }
    }
}

// ------------------- persistent recurrence chain -------------------
// 128 blocks, 256 threads. Block (g = blk>>1, bgrp = blk&1) owns
//   gate rows {q*512 + g*8 + jl : q in 0..3, jl in 0..7}  (32 rows)
//   batches   [bgrp*32, bgrp*32+32)
// W slice kept in smem for all 512 steps, packed as {w,w} f32x2 pairs in an
// interleaved layout so each warp's 4 per-kk W loads hit one contiguous 64B line.
// Thread (kg=tid>>5, rg=(tid>>3)&3, bg=tid&7): K-chunk kg*64, gate-q rg, batches bg*4.
// c state lives in registers of threads 0..127 across all steps.
//
// smem map (dynamic, 198656 B):
//   [0,      131072)  W packed pairs: k*256 + (jl>>1)*64 + q*16 + (jl&1)*8
//   [131072, 196608)  per-warp h slice (8KB each), reused as reduction scratch
//   [196608, 198656)  staged Xu[t+1]
__global__ void __launch_bounds__(256, 1) chain_kernel(
    const float* __restrict__ W_hh, const float* __restrict__ W_ih,
    const float* __restrict__ W_in, const float* __restrict__ b_in,
    const float* __restrict__ b_ih, const float* __restrict__ b_hh,
    const float* __restrict__ c0)
{
    extern __shared__ __align__(16) char smem[];
    char*  Hbase = smem + 131072;
    float* XuS   = (float*)(smem + 196608);

    const int tid  = threadIdx.x;
    const int blk  = blockIdx.x;
    const int g    = blk >> 1;
    const int bgrp = blk & 1;
    const int kg = tid >> 5, lane = tid & 31;
    const int rg = (tid >> 3) & 3, bg = tid & 7;

    // ---- one-time init: load + pack W_hh slice ----
    for (int e = tid; e < 32 * 512; e += 256) {
        int r = e >> 9, k = e & 511;          // threads sweep k contiguously -> coalesced
        int q = r >> 3, jl = r & 7;
        float w = W_hh[(size_t)(q * 512 + g * 8 + jl) * 512 + k];
        *(float2*)(smem + k * 256 + (jl >> 1) * 64 + q * 16 + (jl & 1) * 8)
            = make_float2(w, w);
    }
    // c state registers for pointwise threads
    float cA = 0.f, cB = 0.f;
    int J = 0, B0 = 0;
    if (tid < 128) {
        J  = g * 8 + (tid >> 4);
        B0 = bgrp * 32 + (tid & 15) * 2;
        cA = c0[(size_t)B0 * 512 + J];
        cB = c0[(size_t)(B0 + 1) * 512 + J];
    }
    __syncthreads();

    char* hb = Hbase + kg * 8192;   // this warp's private h slice / scratch

    for (int t = 0; t < SL; ++t) {
        // ---- stage Xu[t+1] (cross-SM data -> bypass L1) ----
        {
            const float2* xsrc = (const float2*)g_Xu[(t + 1) & 1];
            ((float2*)XuS)[tid] = __ldcg(&xsrc[tid]);
        }
        // ---- stage h_t slice: warp kg loads k in [kg*64,+64), b in [bgrp*32,+32) ----
        {
            const float* hsrc = g_hT[t & 1];
            #pragma unroll
            for (int it = 0; it < 16; ++it) {
                int idx = lane + 32 * it;
                int kkl = idx >> 3, b4 = (idx & 7) * 4;
                float4 v = __ldcg((const float4*)(hsrc
                              + (size_t)(kg * 64 + kkl) * 64 + bgrp * 32 + b4));
                *(float4*)(hb + kkl * 128 + b4 * 4) = v;
            }
        }
        __syncwarp();   // h slice is warp-private

        // ---- gate GEMV partials: 8 rows x 4 batches per thread, FFMA2 ----
        unsigned long long acc[8][2];
        #pragma unroll
        for (int jl = 0; jl < 8; ++jl) { acc[jl][0] = 0ull; acc[jl][1] = 0ull; }

        const char* wk = smem + kg * 64 * 256 + rg * 16;
        #pragma unroll 2
        for (int kkl = 0; kkl < 64; ++kkl) {
            ulonglong2 hp = *(const ulonglong2*)(hb + kkl * 128 + bg * 16);
            const char* wr = wk + kkl * 256;
            #pragma unroll
            for (int i = 0; i < 4; ++i) {
                ulonglong2 wp = *(const ulonglong2*)(wr + i * 64);
                ffma2(acc[2*i  ][0], wp.x, hp.x);
                ffma2(acc[2*i  ][1], wp.x, hp.y);
                ffma2(acc[2*i+1][0], wp.y, hp.x);
                ffma2(acc[2*i+1][1], wp.y, hp.y);
            }
        }
        __syncwarp();   // all lanes done reading h before overwriting as scratch
        // partials -> own warp's region: slot (r_loc*16 + bpair)*8 bytes
        #pragma unroll
        for (int jl = 0; jl < 8; ++jl) {
            int r = rg * 8 + jl;
            *(ulonglong2*)(hb + (r * 16 + bg * 2) * 8)
                = make_ulonglong2(acc[jl][0], acc[jl][1]);
        }
        __syncthreads();

        // ---- reduce over 8 K-chunks + LSTM pointwise (threads 0..127) ----
        if (tid < 128) {
            int jl = tid >> 4, bp = tid & 15;   // (J = g*8+jl, batches 2bp,2bp+1)
            float2 gate[4];
            #pragma unroll
            for (int q = 0; q < 4; ++q) {
                int r = q * 8 + jl;
                float sx = 0.f, sy = 0.f;
                #pragma unroll
                for (int kk = 0; kk < 8; ++kk) {
                    float2 p = *(const float2*)(Hbase + kk * 8192 + (r * 16 + bp) * 8);
                    sx += p.x; sy += p.y;
                }
                float xg = __ldcg(&g_XG[t & 1][q * 512 + g * 8 + jl]);
                gate[q] = make_float2(sx + xg, sy + xg);
            }
            // gates: q=0 i, 1 f, 2 g, 3 o
            cA = fmaf(sigm_f(gate[1].x), cA, sigm_f(gate[0].x) * tanh_f(gate[2].x));
            cB = fmaf(sigm_f(gate[1].y), cB, sigm_f(gate[0].y) * tanh_f(gate[2].y));
            float hA = sigm_f(gate[3].x) * tanh_f(cA);
            float hB = sigm_f(gate[3].y) * tanh_f(cB);
            *(float2*)(g_hT[(t + 1) & 1] + (size_t)J * 64 + B0) = make_float2(hA, hB);
            g_Hs[((size_t)t * 64 + B0) * 512 + J]     = hA;
            g_Hs[((size_t)t * 64 + B0 + 1) * 512 + J] = hB;
        }
        // ---- pipelined XG[t+1] / Xu[t+2]: 20 rows per block, 8 threads/row ----
        if (tid < 160) {
            int rr = tid >> 3, l8 = tid & 7;
            int R = blk * 20 + rr;                       // 0..2559
            const float* w = (R < 2048) ? (W_ih + (size_t)R * 512)
                                        : (W_in + (size_t)(R - 2048) * 512);
            float a = 0.f;
            int k0 = l8 * 64;
            #pragma unroll
            for (int i = 0; i < 16; ++i) {
                float4 wv = __ldg((const float4*)(w + k0 + i * 4));
                float4 xv = *(const float4*)(XuS + k0 + i * 4);
                a = fmaf(wv.x, xv.x, a); a = fmaf(wv.y, xv.y, a);
                a = fmaf(wv.z, xv.z, a); a = fmaf(wv.w, xv.w, a);
            }
            a += __shfl_down_sync(0xffffffffu, a, 4, 8);
            a += __shfl_down_sync(0xffffffffu, a, 2, 8);
            a += __shfl_down_sync(0xffffffffu, a, 1, 8);
            if (l8 == 0) {
                if (R < 2048) g_XG[(t + 1) & 1][R] = a + b_ih[R] + b_hh[R];
                else          g_Xu[t & 1][R - 2048] = sigm_f(a + b_in[R - 2048]);
            }
        }
        grid_barrier();
    }
}

// ------------------- SGEMM NT: C[M][512] = A[M][512] * W[512][512]^T + bias -------------------
__global__ void __launch_bounds__(256) sgemm_nt(
    const float* __restrict__ A, const float* __restrict__ W,
    const float* __restrict__ bias, float* __restrict__ C)
{
    __shared__ __align__(16) float As[8][128];
    __shared__ __align__(16) float Ws[8][128];
    int bm = blockIdx.y << 7, bn = blockIdx.x << 7;
    int tid = threadIdx.x;
    int tx = tid & 15, ty = tid >> 4;
    int lr = tid >> 1, lc = (tid & 1) << 2;

    float acc[8][8];
    #pragma unroll
    for (int i = 0; i < 8; i++)
        #pragma unroll
        for (int j = 0; j < 8; j++) acc[i][j] = 0.f;

    for (int k0 = 0; k0 < 512; k0 += 8) {
        float4 av = *(const float4*)&A[(size_t)(bm + lr) * 512 + k0 + lc];
        float4 wv = *(const float4*)&W[(size_t)(bn + lr) * 512 + k0 + lc];
        As[lc + 0][lr] = av.x; As[lc + 1][lr] = av.y;
        As[lc + 2][lr] = av.z; As[lc + 3][lr] = av.w;
        Ws[lc + 0][lr] = wv.x; Ws[lc + 1][lr] = wv.y;
        Ws[lc + 2][lr] = wv.z; Ws[lc + 3][lr] = wv.w;
        __syncthreads();
        #pragma unroll
        for (int kk = 0; kk < 8; kk++) {
            float a[8], bb[8];
            *(float4*)&a[0]  = *(const float4*)&As[kk][ty * 8];
            *(float4*)&a[4]  = *(const float4*)&As[kk][ty * 8 + 4];
            *(float4*)&bb[0] = *(const float4*)&Ws[kk][tx * 8];
            *(float4*)&bb[4] = *(const float4*)&Ws[kk][tx * 8 + 4];
            #pragma unroll
            for (int i = 0; i < 8; i++)
                #pragma unroll
                for (int j = 0; j < 8; j++)
                    acc[i][j] = fmaf(a[i], bb[j], acc[i][j]);
        }
        __syncthreads();
    }
    #pragma unroll
    for (int i = 0; i < 8; i++) {
        size_t off = (size_t)(bm + ty * 8 + i) * 512 + bn + tx * 8;
        #pragma unroll
        for (int j = 0; j < 8; j++)
            C[off + j] = acc[i][j] + bias[bn + tx * 8 + j];
    }
}

// ------------------- attention: u[b,t,s] = tanh(K1[b,s,:]+Q[t,b,:]) . v + b_v -------------------
__global__ void __launch_bounds__(1024) attn_kernel(
    const float* __restrict__ v, const float* __restrict__ b_v,
    const unsigned int* __restrict__ mask32, float* __restrict__ out)
{
    __shared__ float Ksh[32][65];
    __shared__ float Qsh[32][65];
    __shared__ float vsh[64];
    int b  = blockIdx.z;
    int t0 = blockIdx.y << 5;
    int s0 = blockIdx.x << 5;
    int tid = threadIdx.x;
    int sl = tid & 31, tl = tid >> 5;

    float acc = 0.f;
    for (int h0 = 0; h0 < 512; h0 += 64) {
        if (tid < 64) vsh[tid] = v[h0 + tid];
        #pragma unroll
        for (int i = 0; i < 2; i++) {
            int id = tid + i * 1024;
            int row = id >> 6, cc = id & 63;
            Ksh[row][cc] = g_K1[((size_t)b * 512 + s0 + row) * 512 + h0 + cc];
            Qsh[row][cc] = g_Q[((size_t)(t0 + row) * 64 + b) * 512 + h0 + cc];
        }
        __syncthreads();
        #pragma unroll
        for (int h = 0; h < 64; h++) {
            float x = Ksh[sl][h] + Qsh[tl][h];
            acc = fmaf(tanh_f(x), vsh[h], acc);
        }
        __syncthreads();
    }
    float u = acc + b_v[0];
    int s = s0 + sl;
    if (mask32[b * 512 + s] == 0u) u = -1e9f;
    out[((size_t)b * 512 + t0 + tl) * 512 + s] = u;
}

// ------------------- argmax over last dim (first-max tie rule) -------------------
__global__ void __launch_bounds__(256) argmax_kernel(
    const float* __restrict__ logits, float* __restrict__ outf,
    int* __restrict__ outi, int as_float)
{
    int row = blockIdx.x * 8 + (threadIdx.x >> 5);
    int lane = threadIdx.x & 31;
    const float* p = logits + (size_t)row * 512;
    float best = -INFINITY; int bi = 0;
    for (int s = lane; s < 512; s += 32) {
        float vv = p[s];
        if (vv > best) { best = vv; bi = s; }
    }
    #pragma unroll
    for (int off = 16; off; off >>= 1) {
        float ov = __shfl_down_sync(0xffffffffu, best, off);
        int   oi = __shfl_down_sync(0xffffffffu, bi,   off);
        if (ov > best || (ov == best && oi < bi)) { best = ov; bi = oi; }
    }
    if (lane == 0) {
        if (as_float) outf[row] = (float)bi;
        else          outi[row] = bi;
    }
}

// ------------------- launcher -------------------
extern "C" void kernel_launch(void* const* d_in, const int* in_sizes, int n_in,
                              void* d_out, int out_size) {
    const float* enc  = (const float*)d_in[0];
    const unsigned int* mask32 = (const unsigned int*)d_in[1];
    const float* h0   = (const float*)d_in[2];
    const float* c0   = (const float*)d_in[3];
    const float* W_in = (const float*)d_in[4];
    const float* b_in = (const float*)d_in[5];
    const float* W_ih = (const float*)d_in[6];
    const float* b_ih = (const float*)d_in[7];
    const float* W_hh = (const float*)d_in[8];
    const float* b_hh = (const float*)d_in[9];
    const float* W1   = (const float*)d_in[10];
    const float* b1   = (const float*)d_in[11];
    const float* W2   = (const float*)d_in[12];
    const float* b2   = (const float*)d_in[13];
    const float* v    = (const float*)d_in[14];
    const float* b_v  = (const float*)d_in[15];
    (void)in_sizes; (void)n_in;

    float *pK1, *pQ, *pHs, *pL;
    cudaGetSymbolAddress((void**)&pK1, g_K1);
    cudaGetSymbolAddress((void**)&pQ,  g_Q);
    cudaGetSymbolAddress((void**)&pHs, g_Hs);
    cudaGetSymbolAddress((void**)&pL,  g_L);

    const int CHAIN_SMEM = 198656;
    cudaFuncSetAttribute(chain_kernel,
                         cudaFuncAttributeMaxDynamicSharedMemorySize, CHAIN_SMEM);

    prologue_kernel<<<21, 256>>>(h0, W_in, b_in, W_ih, b_ih, b_hh);
    sgemm_nt<<<dim3(4, 256), 256>>>(enc, W1, b1, pK1);          // K1

    chain_kernel<<<NBLK, 256, CHAIN_SMEM>>>(W_hh, W_ih, W_in, b_in, b_ih, b_hh, c0);

    sgemm_nt<<<dim3(4, 256), 256>>>(pHs, W2, b2, pQ);           // Q

    const long long NL = (long long)BB * SL * SL;               // 16,777,216
    float* ldst = ((long long)out_size >= NL) ? (float*)d_out : pL;
    attn_kernel<<<dim3(16, 16, 64), 1024>>>(v, b_v, mask32, ldst);

    if ((long long)out_size >= NL + BB * SL) {
        argmax_kernel<<<4096, 256>>>(ldst, (float*)d_out + NL, nullptr, 1);
    } else if ((long long)out_size < NL) {
        argmax_kernel<<<4096, 256>>>(ldst, nullptr, (int*)d_out, 0);
    }
}

// round 7
// speedup vs baseline: 1.5117x; 1.1405x over previous
#include <cuda_runtime.h>
#include <math.h>

// Problem constants
static const int BB = 64;    // batch
static const int SL = 512;   // sequence length
static const int HD = 512;   // hidden
static const int G4 = 2048;  // 4*H gates
#define NBLK 128             // persistent blocks (<=148 SMs -> all resident)

// ------------------- device scratch (no allocations allowed) -------------------
__device__ float g_K1[(size_t)BB * SL * HD];   // key projection, row = b*SL+s
__device__ float g_Q [(size_t)SL * BB * HD];   // query,          row = t*BB+b
__device__ float g_Hs[(size_t)SL * BB * HD];   // h sequence,     row = t*BB+b
__device__ float g_hT[2][HD * BB];             // transposed h (double buffer) [j][b]
__device__ float g_Xu[2][HD];                  // x' chain (batch independent)
__device__ float g_XG[2][G4];                  // XG[t] = Xu[t]@W_ih^T + b_ih + b_hh
__device__ float g_L [(size_t)BB * SL * SL];   // logits fallback scratch

// flag-array grid barrier (no atomics). Tokens are compared by EQUALITY and are
// monotonic within a launch (1..SL-1); the last-step barrier is skipped, so stale
// values from a previous graph replay (<= SL-1) never equal the first token seen
// before this replay overwrites them.
__device__ unsigned int g_flags[NBLK];
__device__ unsigned int g_go;

// ------------------- accurate fast activations (flag-independent) -------------------
__device__ __forceinline__ float sigm_f(float x) {
    float e = __expf(-x);
    return __fdividef(1.0f, 1.0f + e);
}
__device__ __forceinline__ float tanh_f(float x) {
    float e = __expf(2.0f * x);                 // +inf for big x -> 1, 0 for very negative -> -1
    return 1.0f - __fdividef(2.0f, e + 1.0f);
}

// packed fp32x2 FMA (FFMA2) -- not emitted by ptxas from C++, PTX-only
__device__ __forceinline__ void ffma2(unsigned long long& d, unsigned long long a,
                                      unsigned long long b) {
    asm("fma.rn.f32x2 %0, %1, %2, %0;" : "+l"(d) : "l"(a), "l"(b));
}

// device-wide barrier, token-based. All NBLK blocks resident (1 CTA/SM via smem).
__device__ __forceinline__ void grid_barrier_tok(unsigned int tok) {
    __syncthreads();                               // all block stores done
    if (threadIdx.x == 0) {
        __threadfence();                           // publish to L2
        ((volatile unsigned int*)g_flags)[blockIdx.x] = tok;
    }
    if (blockIdx.x == 0) {
        if (threadIdx.x < NBLK) {
            while (((volatile unsigned int*)g_flags)[threadIdx.x] != tok) { }
        }
        __syncthreads();
        if (threadIdx.x == 0) {
            __threadfence();
            *((volatile unsigned int*)&g_go) = tok;
        }
    }
    if (threadIdx.x == 0) {
        while (*((volatile unsigned int*)&g_go) != tok) { }
        __threadfence();
    }
    __syncthreads();
}

// ------------------- prologue: Xu[0], Xu[1], XG[0], transpose h0 -------------------
__global__ void __launch_bounds__(256) prologue_kernel(
    const float* __restrict__ h0,
    const float* __restrict__ W_in, const float* __restrict__ b_in,
    const float* __restrict__ W_ih, const float* __restrict__ b_ih,
    const float* __restrict__ b_hh)
{
    int blk = blockIdx.x, tid = threadIdx.x;
    if (blk == 0) {
        __shared__ float x0s[HD];
        for (int i = tid; i < HD; i += 256) {
            float x = sigm_f(b_in[i]);
            x0s[i] = x;
            g_Xu[0][i] = x;
        }
        __syncthreads();
        for (int row = tid; row < HD; row += 256) {
            float acc = b_in[row];
            const float* wr = W_in + (size_t)row * HD;
            for (int k = 0; k < HD; k += 4) {
                float4 w4 = *(const float4*)&wr[k];
                acc = fmaf(x0s[k+0], w4.x, acc);
                acc = fmaf(x0s[k+1], w4.y, acc);
                acc = fmaf(x0s[k+2], w4.z, acc);
                acc = fmaf(x0s[k+3], w4.w, acc);
            }
            g_Xu[1][row] = sigm_f(acc);
        }
    } else if (blk <= 16) {
        __shared__ float x0s[HD];
        for (int i = tid; i < HD; i += 256) x0s[i] = sigm_f(b_in[i]);
        __syncthreads();
        if (tid < 128) {
            int row = (blk - 1) * 128 + tid;
            float acc = b_ih[row] + b_hh[row];
            const float* wr = W_ih + (size_t)row * HD;
            for (int k = 0; k < HD; k += 4) {
                float4 w4 = *(const float4*)&wr[k];
                acc = fmaf(x0s[k+0], w4.x, acc);
                acc = fmaf(x0s[k+1], w4.y, acc);
                acc = fmaf(x0s[k+2], w4.z, acc);
                acc = fmaf(x0s[k+3], w4.w, acc);
            }
            g_XG[0][row] = acc;
        }
    } else if (blk <= 20) {
        int j0 = (blk - 17) * 128;
        for (int idx = tid; idx < 128 * BB; idx += 256) {
            int j = j0 + (idx >> 6), b = idx & 63;
            g_hT[0][j * BB + b] = h0[(size_t)b * HD + j];
        }
    }
}

// ------------------- persistent recurrence chain -------------------
// 128 blocks, 256 threads. Block (g = blk>>1, bgrp = blk&1) owns
//   gate rows {q*512 + g*8 + jl : q in 0..3, jl in 0..7}  (32 rows)
//   batches   [bgrp*32, bgrp*32+32)
// W slice smem-resident all 512 steps, packed {w,w} f32x2 pairs.
// Thread (kg=tid>>5, rg=(tid>>3)&3, bg=tid&7): K-chunk kg*64, gate-q rg, batches bg*4.
// Warps 0-3 post-GEMV: reduce + LSTM pointwise. Warps 4-7 post-GEMV: XG/Xu pipeline
// (concurrent, not serialized).
// smem map (dynamic, 198656 B):
//   [0,      131072)  W packed pairs: k*256 + (jl>>1)*64 + q*16 + (jl&1)*8
//   [131072, 196608)  per-warp h slice (8KB each), reused as reduction scratch
//   [196608, 198656)  staged Xu[t+1]
__global__ void __launch_bounds__(256, 1) chain_kernel(
    const float* __restrict__ W_hh, const float* __restrict__ W_ih,
    const float* __restrict__ W_in, const float* __restrict__ b_in,
    const float* __restrict__ b_ih, const float* __restrict__ b_hh,
    const float* __restrict__ c0)
{
    extern __shared__ __align__(16) char smem[];
    char*  Hbase = smem + 131072;
    float* XuS   = (float*)(smem + 196608);

    const int tid  = threadIdx.x;
    const int blk  = blockIdx.x;
    const int g    = blk >> 1;
    const int bgrp = blk & 1;
    const int kg = tid >> 5, lane = tid & 31;
    const int rg = (tid >> 3) & 3, bg = tid & 7;

    // ---- one-time init: load + pack W_hh slice ----
    for (int e = tid; e < 32 * 512; e += 256) {
        int r = e >> 9, k = e & 511;
        int q = r >> 3, jl = r & 7;
        float w = W_hh[(size_t)(q * 512 + g * 8 + jl) * 512 + k];
        *(float2*)(smem + k * 256 + (jl >> 1) * 64 + q * 16 + (jl & 1) * 8)
            = make_float2(w, w);
    }
    // c state registers for pointwise threads
    float cA = 0.f, cB = 0.f;
    int J = 0, B0 = 0;
    if (tid < 128) {
        J  = g * 8 + (tid >> 4);
        B0 = bgrp * 32 + (tid & 15) * 2;
        cA = c0[(size_t)B0 * 512 + J];
        cB = c0[(size_t)(B0 + 1) * 512 + J];
    }
    __syncthreads();

    char* hb = Hbase + kg * 8192;   // this warp's private h slice / scratch

    for (int t = 0; t < SL; ++t) {
        // ---- stage Xu[t+1] (cross-SM data -> bypass L1) ----
        {
            const float2* xsrc = (const float2*)g_Xu[(t + 1) & 1];
            ((float2*)XuS)[tid] = __ldcg(&xsrc[tid]);
        }
        // ---- stage h_t slice: warp kg loads k in [kg*64,+64), b in [bgrp*32,+32) ----
        {
            const float* hsrc = g_hT[t & 1];
            #pragma unroll
            for (int it = 0; it < 16; ++it) {
                int idx = lane + 32 * it;
                int kkl = idx >> 3, b4 = (idx & 7) * 4;
                float4 v = __ldcg((const float4*)(hsrc
                              + (size_t)(kg * 64 + kkl) * 64 + bgrp * 32 + b4));
                *(float4*)(hb + kkl * 128 + b4 * 4) = v;
            }
        }
        __syncwarp();   // h slice is warp-private

        // ---- gate GEMV partials: 8 rows x 4 batches per thread, FFMA2 ----
        unsigned long long acc[8][2];
        #pragma unroll
        for (int jl = 0; jl < 8; ++jl) { acc[jl][0] = 0ull; acc[jl][1] = 0ull; }

        const char* wk = smem + kg * 64 * 256 + rg * 16;
        #pragma unroll 4
        for (int kkl = 0; kkl < 64; ++kkl) {
            ulonglong2 hp = *(const ulonglong2*)(hb + kkl * 128 + bg * 16);
            const char* wr = wk + kkl * 256;
            #pragma unroll
            for (int i = 0; i < 4; ++i) {
                ulonglong2 wp = *(const ulonglong2*)(wr + i * 64);
                ffma2(acc[2*i  ][0], wp.x, hp.x);
                ffma2(acc[2*i  ][1], wp.x, hp.y);
                ffma2(acc[2*i+1][0], wp.y, hp.x);
                ffma2(acc[2*i+1][1], wp.y, hp.y);
            }
        }
        __syncwarp();   // all lanes done reading h before overwriting as scratch
        #pragma unroll
        for (int jl = 0; jl < 8; ++jl) {
            int r = rg * 8 + jl;
            *(ulonglong2*)(hb + (r * 16 + bg * 2) * 8)
                = make_ulonglong2(acc[jl][0], acc[jl][1]);
        }
        __syncthreads();

        if (tid < 128) {
            // ---- warps 0-3: reduce over 8 K-chunks + LSTM pointwise ----
            int jl = tid >> 4, bp = tid & 15;   // (J = g*8+jl, batches 2bp,2bp+1)
            float2 gate[4];
            #pragma unroll
            for (int q = 0; q < 4; ++q) {
                int r = q * 8 + jl;
                float sx = 0.f, sy = 0.f;
                #pragma unroll
                for (int kk = 0; kk < 8; ++kk) {
                    float2 p = *(const float2*)(Hbase + kk * 8192 + (r * 16 + bp) * 8);
                    sx += p.x; sy += p.y;
                }
                float xg = __ldcg(&g_XG[t & 1][q * 512 + g * 8 + jl]);
                gate[q] = make_float2(sx + xg, sy + xg);
            }
            cA = fmaf(sigm_f(gate[1].x), cA, sigm_f(gate[0].x) * tanh_f(gate[2].x));
            cB = fmaf(sigm_f(gate[1].y), cB, sigm_f(gate[0].y) * tanh_f(gate[2].y));
            float hA = sigm_f(gate[3].x) * tanh_f(cA);
            float hB = sigm_f(gate[3].y) * tanh_f(cB);
            *(float2*)(g_hT[(t + 1) & 1] + (size_t)J * 64 + B0) = make_float2(hA, hB);
            g_Hs[((size_t)t * 64 + B0) * 512 + J]     = hA;
            g_Hs[((size_t)t * 64 + B0 + 1) * 512 + J] = hB;
        } else {
            // ---- warps 4-7: pipelined XG[t+1] / Xu[t+2], concurrent with pointwise ----
            // 4 threads per row; k interleaved (l4*16B chunks) -> conflict-free XuS,
            // coalesced W. Groups >= 20 compute a clamped dummy row (full-warp shfl).
            int grp = (tid - 128) >> 2;          // 0..31
            int l4  = tid & 3;
            int valid = (grp < 20);
            int R = blk * 20 + (valid ? grp : 0);
            const float* w = (R < 2048) ? (W_ih + (size_t)R * 512)
                                        : (W_in + (size_t)(R - 2048) * 512);
            float a = 0.f;
            #pragma unroll
            for (int i = 0; i < 32; ++i) {
                int k0 = i * 16 + l4 * 4;
                float4 wv = __ldg((const float4*)(w + k0));
                float4 xv = *(const float4*)(XuS + k0);
                a = fmaf(wv.x, xv.x, a); a = fmaf(wv.y, xv.y, a);
                a = fmaf(wv.z, xv.z, a); a = fmaf(wv.w, xv.w, a);
            }
            a += __shfl_down_sync(0xffffffffu, a, 2, 4);
            a += __shfl_down_sync(0xffffffffu, a, 1, 4);
            if (valid && l4 == 0) {
                if (R < 2048) g_XG[(t + 1) & 1][R] = a + b_ih[R] + b_hh[R];
                else          g_Xu[t & 1][R - 2048] = sigm_f(a + b_in[R - 2048]);
            }
        }
        if (t != SL - 1) grid_barrier_tok((unsigned int)(t + 1));
    }
}

// ------------------- SGEMM NT: C[M][512] = A[M][512] * W[512][512]^T + bias -------------------
__global__ void __launch_bounds__(256) sgemm_nt(
    const float* __restrict__ A, const float* __restrict__ W,
    const float* __restrict__ bias, float* __restrict__ C)
{
    __shared__ __align__(16) float As[8][128];
    __shared__ __align__(16) float Ws[8][128];
    int bm = blockIdx.y << 7, bn = blockIdx.x << 7;
    int tid = threadIdx.x;
    int tx = tid & 15, ty = tid >> 4;
    int lr = tid >> 1, lc = (tid & 1) << 2;

    float acc[8][8];
    #pragma unroll
    for (int i = 0; i < 8; i++)
        #pragma unroll
        for (int j = 0; j < 8; j++) acc[i][j] = 0.f;

    for (int k0 = 0; k0 < 512; k0 += 8) {
        float4 av = *(const float4*)&A[(size_t)(bm + lr) * 512 + k0 + lc];
        float4 wv = *(const float4*)&W[(size_t)(bn + lr) * 512 + k0 + lc];
        As[lc + 0][lr] = av.x; As[lc + 1][lr] = av.y;
        As[lc + 2][lr] = av.z; As[lc + 3][lr] = av.w;
        Ws[lc + 0][lr] = wv.x; Ws[lc + 1][lr] = wv.y;
        Ws[lc + 2][lr] = wv.z; Ws[lc + 3][lr] = wv.w;
        __syncthreads();
        #pragma unroll
        for (int kk = 0; kk < 8; kk++) {
            float a[8], bb[8];
            *(float4*)&a[0]  = *(const float4*)&As[kk][ty * 8];
            *(float4*)&a[4]  = *(const float4*)&As[kk][ty * 8 + 4];
            *(float4*)&bb[0] = *(const float4*)&Ws[kk][tx * 8];
            *(float4*)&bb[4] = *(const float4*)&Ws[kk][tx * 8 + 4];
            #pragma unroll
            for (int i = 0; i < 8; i++)
                #pragma unroll
                for (int j = 0; j < 8; j++)
                    acc[i][j] = fmaf(a[i], bb[j], acc[i][j]);
        }
        __syncthreads();
    }
    #pragma unroll
    for (int i = 0; i < 8; i++) {
        size_t off = (size_t)(bm + ty * 8 + i) * 512 + bn + tx * 8;
        #pragma unroll
        for (int j = 0; j < 8; j++)
            C[off + j] = acc[i][j] + bias[bn + tx * 8 + j];
    }
}

// ------------------- attention: u[b,t,s] = tanh(K1[b,s,:]+Q[t,b,:]) . v + b_v -------------------
__global__ void __launch_bounds__(1024) attn_kernel(
    const float* __restrict__ v, const float* __restrict__ b_v,
    const unsigned int* __restrict__ mask32, float* __restrict__ out)
{
    __shared__ float Ksh[32][65];
    __shared__ float Qsh[32][65];
    __shared__ float vsh[64];
    int b  = blockIdx.z;
    int t0 = blockIdx.y << 5;
    int s0 = blockIdx.x << 5;
    int tid = threadIdx.x;
    int sl = tid & 31, tl = tid >> 5;

    float acc = 0.f;
    for (int h0 = 0; h0 < 512; h0 += 64) {
        if (tid < 64) vsh[tid] = v[h0 + tid];
        #pragma unroll
        for (int i = 0; i < 2; i++) {
            int id = tid + i * 1024;
            int row = id >> 6, cc = id & 63;
            Ksh[row][cc] = g_K1[((size_t)b * 512 + s0 + row) * 512 + h0 + cc];
            Qsh[row][cc] = g_Q[((size_t)(t0 + row) * 64 + b) * 512 + h0 + cc];
        }
        __syncthreads();
        #pragma unroll
        for (int h = 0; h < 64; h++) {
            float x = Ksh[sl][h] + Qsh[tl][h];
            acc = fmaf(tanh_f(x), vsh[h], acc);
        }
        __syncthreads();
    }
    float u = acc + b_v[0];
    int s = s0 + sl;
    if (mask32[b * 512 + s] == 0u) u = -1e9f;
    out[((size_t)b * 512 + t0 + tl) * 512 + s] = u;
}

// ------------------- argmax over last dim (first-max tie rule) -------------------
__global__ void __launch_bounds__(256) argmax_kernel(
    const float* __restrict__ logits, float* __restrict__ outf,
    int* __restrict__ outi, int as_float)
{
    int row = blockIdx.x * 8 + (threadIdx.x >> 5);
    int lane = threadIdx.x & 31;
    const float* p = logits + (size_t)row * 512;
    float best = -INFINITY; int bi = 0;
    for (int s = lane; s < 512; s += 32) {
        float vv = p[s];
        if (vv > best) { best = vv; bi = s; }
    }
    #pragma unroll
    for (int off = 16; off; off >>= 1) {
        float ov = __shfl_down_sync(0xffffffffu, best, off);
        int   oi = __shfl_down_sync(0xffffffffu, bi,   off);
        if (ov > best || (ov == best && oi < bi)) { best = ov; bi = oi; }
    }
    if (lane == 0) {
        if (as_float) outf[row] = (float)bi;
        else          outi[row] = bi;
    }
}

// ------------------- launcher -------------------
extern "C" void kernel_launch(void* const* d_in, const int* in_sizes, int n_in,
                              void* d_out, int out_size) {
    const float* enc  = (const float*)d_in[0];
    const unsigned int* mask32 = (const unsigned int*)d_in[1];
    const float* h0   = (const float*)d_in[2];
    const float* c0   = (const float*)d_in[3];
    const float* W_in = (const float*)d_in[4];
    const float* b_in = (const float*)d_in[5];
    const float* W_ih = (const float*)d_in[6];
    const float* b_ih = (const float*)d_in[7];
    const float* W_hh = (const float*)d_in[8];
    const float* b_hh = (const float*)d_in[9];
    const float* W1   = (const float*)d_in[10];
    const float* b1   = (const float*)d_in[11];
    const float* W2   = (const float*)d_in[12];
    const float* b2   = (const float*)d_in[13];
    const float* v    = (const float*)d_in[14];
    const float* b_v  = (const float*)d_in[15];
    (void)in_sizes; (void)n_in;

    float *pK1, *pQ, *pHs, *pL;
    cudaGetSymbolAddress((void**)&pK1, g_K1);
    cudaGetSymbolAddress((void**)&pQ,  g_Q);
    cudaGetSymbolAddress((void**)&pHs, g_Hs);
    cudaGetSymbolAddress((void**)&pL,  g_L);

    const int CHAIN_SMEM = 198656;
    cudaFuncSetAttribute(chain_kernel,
                         cudaFuncAttributeMaxDynamicSharedMemorySize, CHAIN_SMEM);

    prologue_kernel<<<21, 256>>>(h0, W_in, b_in, W_ih, b_ih, b_hh);
    sgemm_nt<<<dim3(4, 256), 256>>>(enc, W1, b1, pK1);          // K1

    chain_kernel<<<NBLK, 256, CHAIN_SMEM>>>(W_hh, W_ih, W_in, b_in, b_ih, b_hh, c0);

    sgemm_nt<<<dim3(4, 256), 256>>>(pHs, W2, b2, pQ);           // Q

    const long long NL = (long long)BB * SL * SL;               // 16,777,216
    float* ldst = ((long long)out_size >= NL) ? (float*)d_out : pL;
    attn_kernel<<<dim3(16, 16, 64), 1024>>>(v, b_v, mask32, ldst);

    if ((long long)out_size >= NL + BB * SL) {
        argmax_kernel<<<4096, 256>>>(ldst, (float*)d_out + NL, nullptr, 1);
    } else if ((long long)out_size < NL) {
        argmax_kernel<<<4096, 256>>>(ldst, nullptr, (int*)d_out, 0);
    }
}